// round 1
// baseline (speedup 1.0000x reference)
#include <cuda_runtime.h>
#include <cuda_bf16.h>
#include <cstdint>

// Problem constants
#define B_   2
#define CIN_ 256
#define COUT_ 256
#define H_   128
#define W_   128
#define HW_  (H_*W_)
#define KK_  3
#define G_   4
#define CG_  (CIN_/G_)      // 64
#define OCH_ (G_*2*KK_*KK_) // 72
#define KRED (CIN_*KK_*KK_) // 2304
#define NGT  (G_*KK_*KK_)   // 36

// Scratch: offsets in [b,h,w,72] layout
__device__ float g_offset[B_*HW_*OCH_];

// ---------------------------------------------------------------------------
// Kernel 1: 1x1 offset conv.  offset[b,o,h,w] = sum_c x[b,c,h,w]*w[o,c] + bias[o]
// stored as g_offset[(b*HW + h*W + w)*72 + o]
// Block: 256 threads handle 64 consecutive pixels (within one row).
// ---------------------------------------------------------------------------
__global__ void __launch_bounds__(256) offset_kernel(
    const float* __restrict__ x,
    const float* __restrict__ w,
    const float* __restrict__ bias)
{
    __shared__ float xs[16][64];
    __shared__ float ws[72][16];

    const int t   = threadIdx.x;
    const int pix0 = blockIdx.x * 64;            // 512 blocks
    const int b   = pix0 >> 14;                   // /16384
    const int rem = pix0 & (HW_-1);
    const int hh  = rem >> 7;
    const int w0  = rem & (W_-1);

    const int p  = t & 63;
    const int oq = t >> 6;                        // 0..3, 18 outputs each

    float acc[18];
#pragma unroll
    for (int i = 0; i < 18; i++) acc[i] = 0.f;

    const float* xbase = x + (size_t)b * CIN_ * HW_ + hh * W_ + w0;

    for (int c0 = 0; c0 < CIN_; c0 += 16) {
        // load x chunk [16 ch][64 pix], coalesced
#pragma unroll
        for (int r = 0; r < 4; r++) {
            int e  = t + r * 256;
            int kk = e >> 6;
            int pp = e & 63;
            xs[kk][pp] = xbase[(size_t)(c0 + kk) * HW_ + pp];
        }
        // load weight chunk [72][16]
        for (int e = t; e < 72 * 16; e += 256) {
            int o  = e >> 4;
            int kk = e & 15;
            ws[o][kk] = w[o * CIN_ + c0 + kk];
        }
        __syncthreads();
#pragma unroll
        for (int kk = 0; kk < 16; kk++) {
            float xv = xs[kk][p];
#pragma unroll
            for (int i = 0; i < 18; i++)
                acc[i] = fmaf(xv, ws[oq * 18 + i][kk], acc[i]);
        }
        __syncthreads();
    }

    float* ob = g_offset + (size_t)(pix0 + p) * OCH_;
#pragma unroll
    for (int i = 0; i < 18; i++) {
        int o = oq * 18 + i;
        ob[o] = acc[i] + bias[o];
    }
}

// ---------------------------------------------------------------------------
// Kernel 2: deformable conv as implicit GEMM.
//   out[pix, n] = relu( sum_k A[pix,k] * Wd[n,k] ),  k = cin*9 + i*3 + j
//   A[pix,k] = bilinear sample of x[b, cin, h-1+i+dy, w-1+j+dx]  (group = cin/64)
// Block: BM=64 pixels (one half-row) x BN=128 couts, 256 threads, thread tile 4x8.
// Corner indices/weights for all (pixel, group, tap) precomputed in SMEM.
// ---------------------------------------------------------------------------
#define BM 64
#define BN 128
#define BK 8
#define SMEM_BYTES (NGT*BM*4*4*2 + BK*72*4 + BK*132*4)   // 80256

__global__ void __launch_bounds__(256) deform_kernel(
    const float* __restrict__ x,
    const float* __restrict__ wd,
    float* __restrict__ out)
{
    extern __shared__ char smem_raw[];
    int*   sidx = (int*)smem_raw;                  // [4][36][64]
    float* swgt = (float*)smem_raw + NGT * BM;     // [4][36][64] (offset 9216 floats)
    float* As   = swgt + 4 * NGT * BM - 3 * NGT * BM + 3 * NGT * BM; // placeholder fix below

    // explicit layout (floats): sidx 0..9215 (as int), swgt 9216..18431,
    // As 18432..19007 ([8][72]), Bs 19008..20063 ([8][132])
    swgt = (float*)smem_raw + NGT * BM * 4 / 4 * 1;     // = +9216 floats
    swgt = (float*)smem_raw + 9216;
    As   = (float*)smem_raw + 18432;
    float* Bs = (float*)smem_raw + 19008;

    const int t = threadIdx.x;
    const int pix0 = blockIdx.x * BM;             // 512 pixel tiles
    const int nbase = blockIdx.y * BN;            // 0 or 128
    const int b   = pix0 >> 14;
    const int rem = pix0 & (HW_-1);
    const int hh  = rem >> 7;
    const int w0  = rem & (W_-1);

    const float* xb = x + (size_t)b * CIN_ * HW_;

    // ---- setup: bilinear corners for all (gt, p) ----
    for (int e = t; e < NGT * BM; e += 256) {
        int gt  = e >> 6;          // 0..35
        int p   = e & 63;
        int g   = gt / 9;
        int tap = gt - g * 9;
        int ti  = tap / 3;
        int tj  = tap - ti * 3;

        const float* op = g_offset + (size_t)(pix0 + p) * OCH_ + gt * 2;
        float dy = op[0];
        float dx = op[1];

        float ys = (float)(hh - 1 + ti) + dy;
        float xs = (float)(w0 + p - 1 + tj) + dx;

        float y0f = floorf(ys), x0f = floorf(xs);
        int   y0  = (int)y0f,   x0  = (int)x0f;
        float ly  = ys - y0f,   lx  = xs - x0f;
        float hy  = 1.f - ly,   hx  = 1.f - lx;

        int y1 = y0 + 1, x1 = x0 + 1;
        bool vy0 = (y0 >= 0) & (y0 < H_);
        bool vy1 = (y1 >= 0) & (y1 < H_);
        bool vx0 = (x0 >= 0) & (x0 < W_);
        bool vx1 = (x1 >= 0) & (x1 < W_);

        int cy0 = min(max(y0, 0), H_-1);
        int cy1 = min(max(y1, 0), H_-1);
        int cx0 = min(max(x0, 0), W_-1);
        int cx1 = min(max(x1, 0), W_-1);

        int base = gt * BM + p;
        sidx[0*NGT*BM + base] = cy0 * W_ + cx0;
        sidx[1*NGT*BM + base] = cy0 * W_ + cx1;
        sidx[2*NGT*BM + base] = cy1 * W_ + cx0;
        sidx[3*NGT*BM + base] = cy1 * W_ + cx1;
        swgt[0*NGT*BM + base] = (vy0 && vx0) ? hy * hx : 0.f;
        swgt[1*NGT*BM + base] = (vy0 && vx1) ? hy * lx : 0.f;
        swgt[2*NGT*BM + base] = (vy1 && vx0) ? ly * hx : 0.f;
        swgt[3*NGT*BM + base] = (vy1 && vx1) ? ly * lx : 0.f;
    }
    __syncthreads();

    const int tm = t >> 4;   // 0..15 -> pixels tm*4 .. tm*4+3
    const int tn = t & 15;   // 0..15 -> couts  tn*8 .. tn*8+7

    float acc[32];
#pragma unroll
    for (int i = 0; i < 32; i++) acc[i] = 0.f;

    for (int k0 = 0; k0 < KRED; k0 += BK) {
        // ---- A tile: 8 k x 64 pixels, gathered ----
#pragma unroll
        for (int r = 0; r < 2; r++) {
            int e   = t + r * 256;
            int kk  = e >> 6;
            int p   = e & 63;
            int k   = k0 + kk;
            int cin = k / 9;
            int tap = k - cin * 9;
            int g   = cin >> 6;
            int base = (g * 9 + tap) * BM + p;
            const float* xc = xb + (size_t)cin * HW_;
            float v = swgt[0*NGT*BM + base] * __ldg(xc + sidx[0*NGT*BM + base]);
            v = fmaf(swgt[1*NGT*BM + base], __ldg(xc + sidx[1*NGT*BM + base]), v);
            v = fmaf(swgt[2*NGT*BM + base], __ldg(xc + sidx[2*NGT*BM + base]), v);
            v = fmaf(swgt[3*NGT*BM + base], __ldg(xc + sidx[3*NGT*BM + base]), v);
            As[kk * 72 + p] = v;
        }
        // ---- B tile: 8 k x 128 couts (transposed into Bs[kk][n]) ----
        {
            int co = nbase + (t >> 1);
            int kp = (t & 1) * 4;
            float4 wv = *(const float4*)(wd + (size_t)co * KRED + k0 + kp);
            int n = t >> 1;
            Bs[(kp + 0) * 132 + n] = wv.x;
            Bs[(kp + 1) * 132 + n] = wv.y;
            Bs[(kp + 2) * 132 + n] = wv.z;
            Bs[(kp + 3) * 132 + n] = wv.w;
        }
        __syncthreads();

#pragma unroll
        for (int kk = 0; kk < BK; kk++) {
            float4 av  = *(const float4*)(As + kk * 72 + (tm << 2));
            float4 bv0 = *(const float4*)(Bs + kk * 132 + (tn << 3));
            float4 bv1 = *(const float4*)(Bs + kk * 132 + (tn << 3) + 4);
            float ar[4] = {av.x, av.y, av.z, av.w};
            float br[8] = {bv0.x, bv0.y, bv0.z, bv0.w, bv1.x, bv1.y, bv1.z, bv1.w};
#pragma unroll
            for (int i = 0; i < 4; i++)
#pragma unroll
                for (int j = 0; j < 8; j++)
                    acc[i * 8 + j] = fmaf(ar[i], br[j], acc[i * 8 + j]);
        }
        __syncthreads();
    }

    // ---- epilogue: relu + store ----
#pragma unroll
    for (int i = 0; i < 4; i++) {
        int p = (tm << 2) + i;
        size_t pixoff = (size_t)hh * W_ + w0 + p;
#pragma unroll
        for (int j = 0; j < 8; j++) {
            int n = nbase + (tn << 3) + j;
            out[((size_t)b * COUT_ + n) * HW_ + pixoff] = fmaxf(acc[i * 8 + j], 0.f);
        }
    }
}

// ---------------------------------------------------------------------------
extern "C" void kernel_launch(void* const* d_in, const int* in_sizes, int n_in,
                              void* d_out, int out_size)
{
    const float* x      = (const float*)d_in[0];
    const float* w_off  = (const float*)d_in[1];
    const float* b_off  = (const float*)d_in[2];
    const float* w_def  = (const float*)d_in[3];
    float* out = (float*)d_out;

    offset_kernel<<<B_*HW_/64, 256>>>(x, w_off, b_off);

    cudaFuncSetAttribute(deform_kernel,
                         cudaFuncAttributeMaxDynamicSharedMemorySize, SMEM_BYTES);
    dim3 grid(B_*HW_/BM, COUT_/BN);
    deform_kernel<<<grid, 256, SMEM_BYTES>>>(x, w_def, out);
}

// round 2
// speedup vs baseline: 1.8950x; 1.8950x over previous
#include <cuda_runtime.h>
#include <cuda_bf16.h>
#include <cstdint>

#define B_    2
#define CIN_  256
#define COUT_ 256
#define H_    128
#define W_    128
#define HW_   (H_*W_)
#define KK_   3
#define G_    4
#define OCH_  (G_*2*KK_*KK_)   // 72
#define KRED  (CIN_*KK_*KK_)   // 2304
#define NCHUNK (G_*KK_*KK_)    // 36 chunks of 64 k each

// Scratch buffers
__device__ float g_offset[B_*HW_*OCH_];            // [pix][72]
__device__ float g_xt[(size_t)B_*HW_*CIN_];        // NHWC: [b][hw][c]
__device__ float g_wp[(size_t)KRED*COUT_];         // [k'][n], k'=(g*9+tap)*64+cg

// ---------------------------------------------------------------------------
// f32x2 packed math helpers (sm_103a)
// ---------------------------------------------------------------------------
__device__ __forceinline__ unsigned long long ffma2(unsigned long long a,
                                                    unsigned long long b,
                                                    unsigned long long c) {
    unsigned long long d;
    asm("fma.rn.f32x2 %0, %1, %2, %3;" : "=l"(d) : "l"(a), "l"(b), "l"(c));
    return d;
}
__device__ __forceinline__ unsigned long long pack2(float v) {
    unsigned long long d;
    unsigned u = __float_as_uint(v);
    asm("mov.b64 %0, {%1, %1};" : "=l"(d) : "r"(u));
    return d;
}

// ---------------------------------------------------------------------------
// Kernel A: NCHW -> NHWC transpose (32x32 tiles)
// ---------------------------------------------------------------------------
__global__ void __launch_bounds__(256) transpose_kernel(const float* __restrict__ x,
                                                        float* __restrict__ xt)
{
    __shared__ float tl[32][33];
    const int tx = threadIdx.x, ty = threadIdx.y;
    const int bb = blockIdx.z;
    const int hw0 = blockIdx.x * 32;
    const int c0  = blockIdx.y * 32;
#pragma unroll
    for (int r = 0; r < 4; r++)
        tl[ty + 8*r][tx] = x[((size_t)bb*CIN_ + c0 + ty + 8*r)*HW_ + hw0 + tx];
    __syncthreads();
#pragma unroll
    for (int r = 0; r < 4; r++)
        xt[((size_t)bb*HW_ + hw0 + ty + 8*r)*CIN_ + c0 + tx] = tl[tx][ty + 8*r];
}

// ---------------------------------------------------------------------------
// Kernel B: weight permute  wd[n][cin*9+tap] -> wp[(g*9+tap)*64+cg][n]
// ---------------------------------------------------------------------------
__global__ void __launch_bounds__(256) wperm_kernel(const float* __restrict__ wd,
                                                    float* __restrict__ wp)
{
    const int kp = blockIdx.x;          // 0..2303
    const int n  = threadIdx.x;         // 0..255
    const int gt = kp >> 6;             // g*9+tap
    const int cg = kp & 63;
    const int g  = gt / 9;
    const int tap = gt - 9*g;
    const int cin = g*64 + cg;
    wp[(size_t)kp*COUT_ + n] = wd[(size_t)n*KRED + cin*9 + tap];
}

// ---------------------------------------------------------------------------
// Kernel C: 1x1 offset conv (unchanged from R1 — ~25us, fine)
// ---------------------------------------------------------------------------
__global__ void __launch_bounds__(256) offset_kernel(
    const float* __restrict__ x,
    const float* __restrict__ w,
    const float* __restrict__ bias)
{
    __shared__ float xs[16][64];
    __shared__ float ws[72][16];

    const int t    = threadIdx.x;
    const int pix0 = blockIdx.x * 64;
    const int b    = pix0 >> 14;
    const int rem  = pix0 & (HW_-1);
    const int hh   = rem >> 7;
    const int w0   = rem & (W_-1);

    const int p  = t & 63;
    const int oq = t >> 6;

    float acc[18];
#pragma unroll
    for (int i = 0; i < 18; i++) acc[i] = 0.f;

    const float* xbase = x + (size_t)b * CIN_ * HW_ + hh * W_ + w0;

    for (int c0 = 0; c0 < CIN_; c0 += 16) {
#pragma unroll
        for (int r = 0; r < 4; r++) {
            int e  = t + r * 256;
            int kk = e >> 6;
            int pp = e & 63;
            xs[kk][pp] = xbase[(size_t)(c0 + kk) * HW_ + pp];
        }
        for (int e = t; e < 72 * 16; e += 256) {
            int o  = e >> 4;
            int kk = e & 15;
            ws[o][kk] = w[o * CIN_ + c0 + kk];
        }
        __syncthreads();
#pragma unroll
        for (int kk = 0; kk < 16; kk++) {
            float xv = xs[kk][p];
#pragma unroll
            for (int i = 0; i < 18; i++)
                acc[i] = fmaf(xv, ws[oq * 18 + i][kk], acc[i]);
        }
        __syncthreads();
    }

    float* ob = g_offset + (size_t)(pix0 + p) * OCH_;
#pragma unroll
    for (int i = 0; i < 18; i++) {
        int o = oq * 18 + i;
        ob[o] = acc[i] + bias[o];
    }
}

// ---------------------------------------------------------------------------
// Kernel D: deformable conv, implicit GEMM with f32x2 packed FMA.
//   Block = 128 pixels (one image row) x 256 couts, 256 threads (8 warps).
//   K processed in 36 chunks of 64 (one (group,tap) pair each).
//   A-tile gathered NHWC-coalesced; As[k][p] XOR-swizzled for conflict-free
//   LDS.64 pixel-pair loads feeding fma.rn.f32x2.
// SMEM floats: Bs[64][256]=16384 | As[64][128]=8192 | sidx[4][128] | swgt[4][128]
// ---------------------------------------------------------------------------
#define SM_BS   0
#define SM_AS   16384
#define SM_IDX  24576
#define SM_WGT  25088
#define SMEM_FLOATS 25600
#define SMEM_BYTES (SMEM_FLOATS*4)   // 102400

__global__ void __launch_bounds__(256, 1) deform_kernel(
    const float* __restrict__ xt,
    const float* __restrict__ wp,
    float* __restrict__ out)
{
    extern __shared__ float sm[];
    float* Bs   = sm + SM_BS;
    float* As   = sm + SM_AS;
    int*   sidx = (int*)(sm + SM_IDX);
    float* swgt = sm + SM_WGT;

    const int t = threadIdx.x;
    const int pix0 = blockIdx.x * 128;       // one full image row
    const int b    = pix0 >> 14;
    const int hw0  = pix0 & (HW_-1);
    const int hh   = hw0 >> 7;

    // GEMM decomposition: 8 warps = 2 (m) x 4 (n); thread tile 16m x 8n
    const int warp = t >> 5, lane = t & 31;
    const int wm = warp & 1, wn = warp >> 1;
    const int lm = lane & 3, ln = lane >> 2;
    const int p2base = wm*32 + lm;           // pixel-pair index base (pairs at +4i)
    const int nbase  = wn*64 + ln;           // n_j = nbase + 8j

    // gather decomposition
    const int slot = t & 15;                 // float4 slot within 64 channels
    const int gp   = t >> 4;                 // pixel sub-index (0..15)

    const float* xb = xt + (size_t)b * HW_ * CIN_;

    unsigned long long acc[8][8];
#pragma unroll
    for (int i = 0; i < 8; i++)
#pragma unroll
        for (int j = 0; j < 8; j++) acc[i][j] = 0ULL;

    for (int gt = 0; gt < NCHUNK; gt++) {
        const int g   = gt / 9;
        const int tap = gt - 9*g;
        const int ti  = tap / 3;
        const int tj  = tap - 3*ti;
        const int gch = g * 64;

        __syncthreads();   // As/Bs/sidx/swgt free from previous chunk

        // ---- per-chunk bilinear corner setup (128 threads, 1 pixel each) ----
        if (t < 128) {
            const float* op = g_offset + (size_t)(pix0 + t) * OCH_ + gt*2;
            float ys = (float)(hh - 1 + ti) + op[0];
            float xs = (float)(t  - 1 + tj) + op[1];
            float y0f = floorf(ys), x0f = floorf(xs);
            int   y0  = (int)y0f,   x0  = (int)x0f;
            float ly = ys - y0f, lx = xs - x0f;
            float hy = 1.f - ly, hx = 1.f - lx;
            int y1 = y0 + 1, x1 = x0 + 1;
            bool vy0 = (unsigned)y0 < H_, vy1 = (unsigned)y1 < H_;
            bool vx0 = (unsigned)x0 < W_, vx1 = (unsigned)x1 < W_;
            int cy0 = min(max(y0,0),H_-1), cy1 = min(max(y1,0),H_-1);
            int cx0 = min(max(x0,0),W_-1), cx1 = min(max(x1,0),W_-1);
            sidx[0*128 + t] = cy0*W_ + cx0;
            sidx[1*128 + t] = cy0*W_ + cx1;
            sidx[2*128 + t] = cy1*W_ + cx0;
            sidx[3*128 + t] = cy1*W_ + cx1;
            swgt[0*128 + t] = (vy0 && vx0) ? hy*hx : 0.f;
            swgt[1*128 + t] = (vy0 && vx1) ? hy*lx : 0.f;
            swgt[2*128 + t] = (vy1 && vx0) ? ly*hx : 0.f;
            swgt[3*128 + t] = (vy1 && vx1) ? ly*lx : 0.f;
        }
        __syncthreads();

        // ---- gather A chunk: As[cg][p], dense NHWC float4 loads ----
#pragma unroll
        for (int pass = 0; pass < 8; pass++) {
            const int p  = pass*16 + gp;
            const int i0 = sidx[0*128+p], i1 = sidx[1*128+p];
            const int i2 = sidx[2*128+p], i3 = sidx[3*128+p];
            const float w0 = swgt[0*128+p], w1 = swgt[1*128+p];
            const float w2 = swgt[2*128+p], w3 = swgt[3*128+p];
            const int co = gch + slot*4;
            float4 v0 = *(const float4*)(xb + (size_t)i0*CIN_ + co);
            float4 v1 = *(const float4*)(xb + (size_t)i1*CIN_ + co);
            float4 v2 = *(const float4*)(xb + (size_t)i2*CIN_ + co);
            float4 v3 = *(const float4*)(xb + (size_t)i3*CIN_ + co);
            float4 r;
            r.x = fmaf(w3,v3.x, fmaf(w2,v2.x, fmaf(w1,v1.x, w0*v0.x)));
            r.y = fmaf(w3,v3.y, fmaf(w2,v2.y, fmaf(w1,v1.y, w0*v0.y)));
            r.z = fmaf(w3,v3.z, fmaf(w2,v2.z, fmaf(w1,v1.z, w0*v0.z)));
            r.w = fmaf(w3,v3.w, fmaf(w2,v2.w, fmaf(w1,v1.w, w0*v0.w)));
            const int cg  = slot*4;
            const int col = 2*((p>>1) ^ (slot & 7)) + (p & 1);
            As[(cg+0)*128 + col] = r.x;
            As[(cg+1)*128 + col] = r.y;
            As[(cg+2)*128 + col] = r.z;
            As[(cg+3)*128 + col] = r.w;
        }

        // ---- load B chunk: wp rows [gt*64, gt*64+64), 256 wide ----
        {
            const float4* wsrc = (const float4*)(wp + (size_t)gt*64*COUT_);
            float4* bd = (float4*)Bs;
#pragma unroll
            for (int e = 0; e < 16; e++)
                bd[t + e*256] = wsrc[t + e*256];
        }
        __syncthreads();

        // ---- GEMM: 64 k of FFMA2 ----
        for (int k4 = 0; k4 < 16; k4++) {
            const int xm = k4 & 7;
            const float* A0 = As + k4*(4*128);
            const float* B0 = Bs + k4*(4*256) + nbase;
            unsigned off[8];
#pragma unroll
            for (int i = 0; i < 8; i++)
                off[i] = 2u * (unsigned)((p2base + 4*i) ^ xm);
#pragma unroll
            for (int kk = 0; kk < 4; kk++) {
                unsigned long long a2[8], b2[8];
#pragma unroll
                for (int i = 0; i < 8; i++)
                    a2[i] = *(const unsigned long long*)(A0 + kk*128 + off[i]);
#pragma unroll
                for (int j = 0; j < 8; j++)
                    b2[j] = pack2(B0[kk*256 + 8*j]);
#pragma unroll
                for (int i = 0; i < 8; i++)
#pragma unroll
                    for (int j = 0; j < 8; j++)
                        acc[i][j] = ffma2(a2[i], b2[j], acc[i][j]);
            }
        }
    }

    // ---- epilogue: relu + float2 stores (pixel pairs contiguous) ----
    const size_t ob = (size_t)b * COUT_ * HW_ + hw0;
#pragma unroll
    for (int i = 0; i < 8; i++) {
        const int p = 2*(p2base + 4*i);
#pragma unroll
        for (int j = 0; j < 8; j++) {
            const int n = nbase + 8*j;
            float2 v;
            v.x = fmaxf(__uint_as_float((unsigned)(acc[i][j] & 0xffffffffULL)), 0.f);
            v.y = fmaxf(__uint_as_float((unsigned)(acc[i][j] >> 32)), 0.f);
            *(float2*)(out + ob + (size_t)n*HW_ + p) = v;
        }
    }
}

// ---------------------------------------------------------------------------
extern "C" void kernel_launch(void* const* d_in, const int* in_sizes, int n_in,
                              void* d_out, int out_size)
{
    (void)in_sizes; (void)n_in; (void)out_size;
    const float* x     = (const float*)d_in[0];
    const float* w_off = (const float*)d_in[1];
    const float* b_off = (const float*)d_in[2];
    const float* w_def = (const float*)d_in[3];
    float* out = (float*)d_out;

    float* xt; cudaGetSymbolAddress((void**)&xt, g_xt);
    float* wpp; cudaGetSymbolAddress((void**)&wpp, g_wp);

    transpose_kernel<<<dim3(HW_/32, CIN_/32, B_), dim3(32, 8)>>>(x, xt);
    wperm_kernel<<<KRED, 256>>>(w_def, wpp);
    offset_kernel<<<B_*HW_/64, 256>>>(x, w_off, b_off);

    static bool attr_set = false;
    if (!attr_set) {
        cudaFuncSetAttribute(deform_kernel,
                             cudaFuncAttributeMaxDynamicSharedMemorySize, SMEM_BYTES);
        attr_set = true;
    }
    deform_kernel<<<B_*HW_/128, 256, SMEM_BYTES>>>(xt, wpp, out);
}

// round 4
// speedup vs baseline: 3.0915x; 1.6314x over previous
#include <cuda_runtime.h>
#include <cuda_bf16.h>
#include <cstdint>

#define B_    2
#define CIN_  256
#define COUT_ 256
#define H_    128
#define W_    128
#define HW_   (H_*W_)
#define KK_   3
#define G_    4
#define OCH_  (G_*2*KK_*KK_)   // 72
#define KRED  (CIN_*KK_*KK_)   // 2304
#define NCHUNK (G_*KK_*KK_)    // 36 chunks of 64 k each

// Scratch buffers
__device__ float g_offset[B_*HW_*OCH_];                  // [pix][72]
__device__ float g_xt[(size_t)B_*HW_*CIN_];              // NHWC: [b][hw][c]
__device__ __nv_bfloat16 g_wb[(size_t)NCHUNK*2*256*64];  // per chunk: [hi 32KB][lo 32KB] swizzled [n][k]

// ---------------------------------------------------------------------------
// helpers
// ---------------------------------------------------------------------------
__device__ __forceinline__ uint32_t smem_u32(const void* p) {
    uint32_t a;
    asm("{ .reg .u64 t; cvta.to.shared.u64 t, %1; cvt.u32.u64 %0, t; }" : "=r"(a) : "l"(p));
    return a;
}
__device__ __forceinline__ void ldsm_x4(uint32_t r[4], uint32_t addr) {
    asm volatile("ldmatrix.sync.aligned.m8n8.x4.shared.b16 {%0,%1,%2,%3}, [%4];"
                 : "=r"(r[0]), "=r"(r[1]), "=r"(r[2]), "=r"(r[3]) : "r"(addr));
}
__device__ __forceinline__ void mma_bf16(float d[4], const uint32_t a[4],
                                         uint32_t b0, uint32_t b1) {
    asm volatile(
        "mma.sync.aligned.m16n8k16.row.col.f32.bf16.bf16.f32 "
        "{%0,%1,%2,%3}, {%4,%5,%6,%7}, {%8,%9}, {%0,%1,%2,%3};"
        : "+f"(d[0]), "+f"(d[1]), "+f"(d[2]), "+f"(d[3])
        : "r"(a[0]), "r"(a[1]), "r"(a[2]), "r"(a[3]), "r"(b0), "r"(b1));
}

// ---------------------------------------------------------------------------
// Kernel A: NCHW -> NHWC transpose (32x32 tiles)
// ---------------------------------------------------------------------------
__global__ void __launch_bounds__(256) transpose_kernel(const float* __restrict__ x,
                                                        float* __restrict__ xt)
{
    __shared__ float tl[32][33];
    const int tx = threadIdx.x, ty = threadIdx.y;
    const int bb = blockIdx.z;
    const int hw0 = blockIdx.x * 32;
    const int c0  = blockIdx.y * 32;
#pragma unroll
    for (int r = 0; r < 4; r++)
        tl[ty + 8*r][tx] = x[((size_t)bb*CIN_ + c0 + ty + 8*r)*HW_ + hw0 + tx];
    __syncthreads();
#pragma unroll
    for (int r = 0; r < 4; r++)
        xt[((size_t)bb*HW_ + hw0 + ty + 8*r)*CIN_ + c0 + tx] = tl[tx][ty + 8*r];
}

// ---------------------------------------------------------------------------
// Kernel B: weight prepack -> bf16 hi/lo, [n][k] tiles, SW128 swizzled.
// ---------------------------------------------------------------------------
__global__ void __launch_bounds__(256) prepack_kernel(const float* __restrict__ wd,
                                                      __nv_bfloat16* __restrict__ wb)
{
    const int gt = blockIdx.x;
    const int g = gt / 9;
    const int tap = gt - 9*g;
    for (int idx = threadIdx.x; idx < 256*64; idx += 256) {
        const int n  = idx >> 6;
        const int cg = idx & 63;
        float v = wd[(size_t)n*KRED + (g*64 + cg)*9 + tap];
        __nv_bfloat16 h = __float2bfloat16_rn(v);
        __nv_bfloat16 l = __float2bfloat16_rn(v - __bfloat162float(h));
        const int dst = n*64 + (cg ^ ((n & 7) << 3));   // SW128 (bf16 elems)
        wb[(size_t)gt*32768 + dst]          = h;
        wb[(size_t)gt*32768 + 16384 + dst]  = l;
    }
}

// ---------------------------------------------------------------------------
// Kernel C: 1x1 offset conv (fp32)
// ---------------------------------------------------------------------------
__global__ void __launch_bounds__(256) offset_kernel(
    const float* __restrict__ x,
    const float* __restrict__ w,
    const float* __restrict__ bias)
{
    __shared__ float xs[16][64];
    __shared__ float ws[72][16];

    const int t    = threadIdx.x;
    const int pix0 = blockIdx.x * 64;
    const int b    = pix0 >> 14;
    const int rem  = pix0 & (HW_-1);
    const int hh   = rem >> 7;
    const int w0   = rem & (W_-1);

    const int p  = t & 63;
    const int oq = t >> 6;

    float acc[18];
#pragma unroll
    for (int i = 0; i < 18; i++) acc[i] = 0.f;

    const float* xbase = x + (size_t)b * CIN_ * HW_ + hh * W_ + w0;

    for (int c0 = 0; c0 < CIN_; c0 += 16) {
#pragma unroll
        for (int r = 0; r < 4; r++) {
            int e  = t + r * 256;
            int kk = e >> 6;
            int pp = e & 63;
            xs[kk][pp] = xbase[(size_t)(c0 + kk) * HW_ + pp];
        }
        for (int e = t; e < 72 * 16; e += 256) {
            int o  = e >> 4;
            int kk = e & 15;
            ws[o][kk] = w[o * CIN_ + c0 + kk];
        }
        __syncthreads();
#pragma unroll
        for (int kk = 0; kk < 16; kk++) {
            float xv = xs[kk][p];
#pragma unroll
            for (int i = 0; i < 18; i++)
                acc[i] = fmaf(xv, ws[oq * 18 + i][kk], acc[i]);
        }
        __syncthreads();
    }

    float* ob = g_offset + (size_t)(pix0 + p) * OCH_;
#pragma unroll
    for (int i = 0; i < 18; i++) {
        int o = oq * 18 + i;
        ob[o] = acc[i] + bias[o];
    }
}

// ---------------------------------------------------------------------------
// Kernel D: deformable conv on HMMA (mma.sync bf16 hi/lo split, fp32 reg accum)
// Block = 128 pixels x 256 couts, 256 threads (8 warps = 2m x 4n, warp 64x64).
// SMEM (bytes):
//   [0,32768)       Bs_hi  [256 n][64 k] bf16 SW128
//   [32768,65536)   Bs_lo
//   [65536,81920)   As_hi  [128 p][64 k] bf16 SW128
//   [81920,98304)   As_lo
//   [98304,100352)  sidx[4][128]
//   [100352,102400) swgt[4][128]
// ---------------------------------------------------------------------------
#define SM_BHI 0
#define SM_BLO 32768
#define SM_AHI 65536
#define SM_ALO 81920
#define SM_IDX 98304
#define SM_WGT 100352
#define SMEM_BYTES 102400

__global__ void __launch_bounds__(256, 1)
deform_kernel(const float* __restrict__ xt,
              const __nv_bfloat16* __restrict__ wb,
              float* __restrict__ out)
{
    extern __shared__ char sm[];
    const uint32_t sb = smem_u32(sm);

    const int t = threadIdx.x;
    const int warp = t >> 5, lane = t & 31;
    const int pix0 = blockIdx.x * 128;
    const int b    = pix0 >> 14;
    const int hw0  = pix0 & (HW_-1);
    const int hh   = hw0 >> 7;

    int*   sidx = (int*)(sm + SM_IDX);
    float* swgt = (float*)(sm + SM_WGT);

    const int wm = warp & 1, wn = warp >> 1;

    // ldmatrix lane geometry (A: rows = pixels, B: rows = couts)
    const uint32_t rowA  = wm*64 + (lane & 15);
    const uint32_t swzA  = (rowA & 7) << 4;
    const uint32_t kA    = (uint32_t)(lane & 16);           // byte offset
    const uint32_t aBase0 = sb + SM_AHI + rowA*128;

    const uint32_t rowB  = wn*64 + (lane & 7) + ((lane & 16) >> 1);
    const uint32_t swzB  = (rowB & 7) << 4;
    const uint32_t kB    = (uint32_t)((lane & 8) << 1);     // byte offset
    const uint32_t bBase0 = sb + SM_BHI + rowB*128;

    // gather decomposition
    const int slot = t & 15;
    const int gp   = t >> 4;
    const float* xb = xt + (size_t)b * HW_ * CIN_;

    float acc[4][8][4];
#pragma unroll
    for (int i = 0; i < 4; i++)
#pragma unroll
        for (int j = 0; j < 8; j++)
#pragma unroll
            for (int q = 0; q < 4; q++) acc[i][j][q] = 0.f;

    for (int gt = 0; gt < NCHUNK; gt++) {
        const int g   = gt / 9;
        const int tap = gt - 9*g;
        const int ti  = tap / 3;
        const int tj  = tap - 3*ti;
        const int gch = g * 64;

        __syncthreads();   // previous chunk's compute done

        // ---- bilinear corner setup ----
        if (t < 128) {
            const float* op = g_offset + (size_t)(pix0 + t) * OCH_ + gt*2;
            float ys = (float)(hh - 1 + ti) + op[0];
            float xs = (float)(t  - 1 + tj) + op[1];
            float y0f = floorf(ys), x0f = floorf(xs);
            int   y0  = (int)y0f,   x0  = (int)x0f;
            float ly = ys - y0f, lx = xs - x0f;
            float hy = 1.f - ly, hx = 1.f - lx;
            int y1 = y0 + 1, x1 = x0 + 1;
            bool vy0 = (unsigned)y0 < H_, vy1 = (unsigned)y1 < H_;
            bool vx0 = (unsigned)x0 < W_, vx1 = (unsigned)x1 < W_;
            int cy0 = min(max(y0,0),H_-1), cy1 = min(max(y1,0),H_-1);
            int cx0 = min(max(x0,0),W_-1), cx1 = min(max(x1,0),W_-1);
            sidx[0*128 + t] = cy0*W_ + cx0;
            sidx[1*128 + t] = cy0*W_ + cx1;
            sidx[2*128 + t] = cy1*W_ + cx0;
            sidx[3*128 + t] = cy1*W_ + cx1;
            swgt[0*128 + t] = (vy0 && vx0) ? hy*hx : 0.f;
            swgt[1*128 + t] = (vy0 && vx1) ? hy*lx : 0.f;
            swgt[2*128 + t] = (vy1 && vx0) ? ly*hx : 0.f;
            swgt[3*128 + t] = (vy1 && vx1) ? ly*lx : 0.f;
        }
        __syncthreads();

        // ---- B copy: 64KB prepacked (hi+lo) -> SMEM ----
        {
            const uint4* bsrc = (const uint4*)(wb + (size_t)gt * 32768);
            uint4* bdst = (uint4*)(sm + SM_BHI);
#pragma unroll
            for (int e = 0; e < 16; e++)
                bdst[t + e*256] = bsrc[t + e*256];
        }

        // ---- A gather: bilinear sample, bf16 split, swizzled STS ----
#pragma unroll
        for (int pass = 0; pass < 8; pass++) {
            const int p  = pass*16 + gp;
            const int i0 = sidx[0*128+p], i1 = sidx[1*128+p];
            const int i2 = sidx[2*128+p], i3 = sidx[3*128+p];
            const float w0 = swgt[0*128+p], w1 = swgt[1*128+p];
            const float w2 = swgt[2*128+p], w3 = swgt[3*128+p];
            const int co = gch + slot*4;
            float4 v0 = *(const float4*)(xb + (size_t)i0*CIN_ + co);
            float4 v1 = *(const float4*)(xb + (size_t)i1*CIN_ + co);
            float4 v2 = *(const float4*)(xb + (size_t)i2*CIN_ + co);
            float4 v3 = *(const float4*)(xb + (size_t)i3*CIN_ + co);
            float r0 = fmaf(w3,v3.x, fmaf(w2,v2.x, fmaf(w1,v1.x, w0*v0.x)));
            float r1 = fmaf(w3,v3.y, fmaf(w2,v2.y, fmaf(w1,v1.y, w0*v0.y)));
            float r2 = fmaf(w3,v3.z, fmaf(w2,v2.z, fmaf(w1,v1.z, w0*v0.z)));
            float r3 = fmaf(w3,v3.w, fmaf(w2,v2.w, fmaf(w1,v1.w, w0*v0.w)));

            __nv_bfloat16 h0 = __float2bfloat16_rn(r0);
            __nv_bfloat16 h1 = __float2bfloat16_rn(r1);
            __nv_bfloat16 h2 = __float2bfloat16_rn(r2);
            __nv_bfloat16 h3 = __float2bfloat16_rn(r3);
            __nv_bfloat16 l0 = __float2bfloat16_rn(r0 - __bfloat162float(h0));
            __nv_bfloat16 l1 = __float2bfloat16_rn(r1 - __bfloat162float(h1));
            __nv_bfloat16 l2 = __float2bfloat16_rn(r2 - __bfloat162float(h2));
            __nv_bfloat16 l3 = __float2bfloat16_rn(r3 - __bfloat162float(h3));

            const uint32_t aoff = (uint32_t)(p*128 + ((slot*8) ^ ((p & 7) << 4)));
            __nv_bfloat162 hA(h0, h1), hB(h2, h3), lA(l0, l1), lB(l2, l3);
            uint2 hv, lv;
            hv.x = *(uint32_t*)&hA; hv.y = *(uint32_t*)&hB;
            lv.x = *(uint32_t*)&lA; lv.y = *(uint32_t*)&lB;
            *(uint2*)(sm + SM_AHI + aoff) = hv;
            *(uint2*)(sm + SM_ALO + aoff) = lv;
        }
        __syncthreads();

        // ---- compute: 3 split terms x 4 k-steps ----
#pragma unroll
        for (int term = 0; term < 3; term++) {
            const uint32_t aBase = aBase0 + (term == 2 ? 16384u : 0u);
            const uint32_t bBase = bBase0 + (term == 1 ? 32768u : 0u);
#pragma unroll
            for (int ks = 0; ks < 4; ks++) {
                const uint32_t kbyte = (uint32_t)(ks * 32);
                uint32_t a[4][4], bf[4][4];
#pragma unroll
                for (int mt = 0; mt < 4; mt++)
                    ldsm_x4(a[mt], aBase + mt*2048 + ((kbyte + kA) ^ swzA));
#pragma unroll
                for (int np = 0; np < 4; np++)
                    ldsm_x4(bf[np], bBase + np*2048 + ((kbyte + kB) ^ swzB));
#pragma unroll
                for (int mt = 0; mt < 4; mt++)
#pragma unroll
                    for (int nt = 0; nt < 8; nt++)
                        mma_bf16(acc[mt][nt], a[mt],
                                 bf[nt >> 1][(nt & 1) * 2],
                                 bf[nt >> 1][(nt & 1) * 2 + 1]);
            }
        }
    }

    // ---- epilogue: relu + store (NCHW) ----
    const size_t ob = (size_t)b * COUT_ * HW_ + hw0;
    const int mrow = wm*64 + (lane >> 2);
    const int ncol = wn*64 + (lane & 3) * 2;
#pragma unroll
    for (int mt = 0; mt < 4; mt++) {
#pragma unroll
        for (int nt = 0; nt < 8; nt++) {
            const int m = mrow + mt*16;
            const int n = ncol + nt*8;
            float* o0 = out + ob + (size_t)n * HW_ + m;
            o0[0]        = fmaxf(acc[mt][nt][0], 0.f);
            o0[HW_]      = fmaxf(acc[mt][nt][1], 0.f);
            o0[8]        = fmaxf(acc[mt][nt][2], 0.f);
            o0[HW_ + 8]  = fmaxf(acc[mt][nt][3], 0.f);
        }
    }
}

// ---------------------------------------------------------------------------
extern "C" void kernel_launch(void* const* d_in, const int* in_sizes, int n_in,
                              void* d_out, int out_size)
{
    (void)in_sizes; (void)n_in; (void)out_size;
    const float* x     = (const float*)d_in[0];
    const float* w_off = (const float*)d_in[1];
    const float* b_off = (const float*)d_in[2];
    const float* w_def = (const float*)d_in[3];
    float* out = (float*)d_out;

    float* xt;           cudaGetSymbolAddress((void**)&xt, g_xt);
    __nv_bfloat16* wbp;  cudaGetSymbolAddress((void**)&wbp, g_wb);

    transpose_kernel<<<dim3(HW_/32, CIN_/32, B_), dim3(32, 8)>>>(x, xt);
    prepack_kernel<<<NCHUNK, 256>>>(w_def, wbp);
    offset_kernel<<<B_*HW_/64, 256>>>(x, w_off, b_off);

    static bool attr_set = false;
    if (!attr_set) {
        cudaFuncSetAttribute(deform_kernel,
                             cudaFuncAttributeMaxDynamicSharedMemorySize, SMEM_BYTES);
        attr_set = true;
    }
    deform_kernel<<<B_*HW_/128, 256, SMEM_BYTES>>>(xt, wbp, out);
}